// round 12
// baseline (speedup 1.0000x reference)
#include <cuda_runtime.h>

#define BATCH 4
#define C1N 128
#define C2N 64
#define NPIX1 16384   // 128*128
#define NPIX2 65536   // 256*256
#define NB 256

// ---- scratch (device globals; zero-init at load; k_fuse re-zeroes g_gaps) ----
__device__ float g_gaps[BATCH * C1N + BATCH * C2N];  // [0,512): x1 sums, [512,768): x2 sums
__device__ __align__(16) float g_pos1[BATCH * NB * 64];   // [b][n][ij]
__device__ __align__(16) float g_pos2[BATCH * NB * 256];  // [b][n][ij]
__device__ __align__(16) float g_spa [BATCH * NPIX2];     // [b][h=n][w=k]
__device__ __align__(16) float g_w3t [BATCH * C2N * C2N]; // [b][c][o]  prefused, transposed
__device__ __align__(16) float g_s3  [C2N];
__device__ __align__(16) float g_t3  [C2N];

__device__ __forceinline__ float ex2f(float x) {   // guaranteed MUFU.EX2
    float r;
    asm("ex2.approx.ftz.f32 %0, %1;" : "=f"(r) : "f"(x));
    return r;
}

// ---- kernel 1: pos1 & pos2 + channel sums; NO in-loop reductions ----
__global__ void __launch_bounds__(256) k_pos(const float* __restrict__ x1,
                                             const float* __restrict__ wp1,
                                             const float* __restrict__ bp1,
                                             const float* __restrict__ x2,
                                             const float* __restrict__ wp2,
                                             const float* __restrict__ bp2) {
    __shared__ __align__(16) float part[8][256];
    __shared__ float cpart[8][16][33];   // padded: conflict-free column reads
    int tid = threadIdx.x, wid = tid >> 5, lane = tid & 31;

    if (blockIdx.x < 256) {
        // ---- pos1: warp owns 16 channels x 256 pixels ----
        int bid = blockIdx.x;
        int b = bid >> 6;
        int p0 = (bid & 63) << 8;
        const float* plane = x1 + (size_t)b * C1N * NPIX1 + p0;
        float d[8];
        #pragma unroll
        for (int k = 0; k < 8; k++) d[k] = 0.f;
        float cs[16];
        #pragma unroll 8
        for (int j = 0; j < 16; j++) {
            int c = wid + 8 * j;
            float w = __ldg(&wp1[c]);
            const float4* cp = (const float4*)(plane + ((size_t)c << 14));
            float4 v0 = cp[lane];
            float4 v1 = cp[lane + 32];
            d[0] = fmaf(w, v0.x, d[0]); d[1] = fmaf(w, v0.y, d[1]);
            d[2] = fmaf(w, v0.z, d[2]); d[3] = fmaf(w, v0.w, d[3]);
            d[4] = fmaf(w, v1.x, d[4]); d[5] = fmaf(w, v1.y, d[5]);
            d[6] = fmaf(w, v1.z, d[6]); d[7] = fmaf(w, v1.w, d[7]);
            cs[j] = ((v0.x + v0.y) + (v0.z + v0.w)) + ((v1.x + v1.y) + (v1.z + v1.w));
        }
        #pragma unroll
        for (int j = 0; j < 16; j++) cpart[wid][j][lane] = cs[j];
        ((float4*)&part[wid][lane * 4])[0]       = make_float4(d[0], d[1], d[2], d[3]);
        ((float4*)&part[wid][128 + lane * 4])[0] = make_float4(d[4], d[5], d[6], d[7]);
        __syncthreads();
        float dot = bp1[0];
        #pragma unroll
        for (int w = 0; w < 8; w++) dot += part[w][tid];
        int p = p0 + tid;
        int y = p >> 7, x = p & 127;
        int n  = ((y >> 3) << 4) | (x >> 3);
        int ij = ((y & 7) << 3) | (x & 7);
        g_pos1[((b << 8) | n) * 64 + ij] = dot;
        if (tid < 128) {                 // channel-sum reduce: thread owns (warp, j)
            int w = tid >> 4, j = tid & 15;
            float s = 0.f;
            #pragma unroll
            for (int l = 0; l < 32; l++) s += cpart[w][j][l];
            atomicAdd(&g_gaps[b * C1N + w + 8 * j], s);
        }
    } else {
        // ---- pos2: warp owns 8 channels x 256 pixels ----
        int bid = blockIdx.x - 256;
        int b = bid >> 8;
        int p0 = (bid & 255) << 8;
        const float* plane = x2 + (size_t)b * C2N * NPIX2 + p0;
        float d[8];
        #pragma unroll
        for (int k = 0; k < 8; k++) d[k] = 0.f;
        float cs[8];
        #pragma unroll
        for (int j = 0; j < 8; j++) {
            int c = wid + 8 * j;
            float w = __ldg(&wp2[c]);
            const float4* cp = (const float4*)(plane + ((size_t)c << 16));
            float4 v0 = cp[lane];
            float4 v1 = cp[lane + 32];
            d[0] = fmaf(w, v0.x, d[0]); d[1] = fmaf(w, v0.y, d[1]);
            d[2] = fmaf(w, v0.z, d[2]); d[3] = fmaf(w, v0.w, d[3]);
            d[4] = fmaf(w, v1.x, d[4]); d[5] = fmaf(w, v1.y, d[5]);
            d[6] = fmaf(w, v1.z, d[6]); d[7] = fmaf(w, v1.w, d[7]);
            cs[j] = ((v0.x + v0.y) + (v0.z + v0.w)) + ((v1.x + v1.y) + (v1.z + v1.w));
        }
        #pragma unroll
        for (int j = 0; j < 8; j++) cpart[wid][j][lane] = cs[j];
        ((float4*)&part[wid][lane * 4])[0]       = make_float4(d[0], d[1], d[2], d[3]);
        ((float4*)&part[wid][128 + lane * 4])[0] = make_float4(d[4], d[5], d[6], d[7]);
        __syncthreads();
        float dot = bp2[0];
        #pragma unroll
        for (int w = 0; w < 8; w++) dot += part[w][tid];
        int p = p0 + tid;
        int y = p >> 8, x = p & 255;
        int n  = ((y >> 4) << 4) | (x >> 4);
        int ij = ((y & 15) << 4) | (x & 15);
        g_pos2[((b << 8) | n) * 256 + ij] = dot;
        if (tid < 64) {
            int w = tid >> 3, j = tid & 7;
            float s = 0.f;
            #pragma unroll
            for (int l = 0; l < 32; l++) s += cpart[w][j][l];
            atomicAdd(&g_gaps[BATCH * C1N + b * C2N + w + 8 * j], s);
        }
    }
}

// ---- kernel 2: mlp -> cw softmax (redundant per CTA) -> prefused w3t/s3/t3 ----
__global__ void __launch_bounds__(256) k_w3(const float* __restrict__ wc1, const float* __restrict__ bc1,
                                            const float* __restrict__ wc2, const float* __restrict__ bc2,
                                            const float* __restrict__ wf,  const float* __restrict__ bf,
                                            const float* __restrict__ gamma, const float* __restrict__ beta) {
    __shared__ float s_m1[256], s_m2[256], s_cw[256];
    int t = threadIdx.x;
    int b = t >> 6, g = (t >> 3) & 7, o = t & 7;
    const float INV1 = 1.f / NPIX1, INV2 = 1.f / NPIX2;
    {
        float a = bc1[o];
        const float* gp = &g_gaps[b * C1N + g * 16];
        #pragma unroll
        for (int c = 0; c < 16; c++) a = fmaf(wc1[o * 16 + c] * INV1, gp[c], a);
        s_m1[t] = fmaxf(a, 0.f);
    }
    {
        float a = bc2[o];
        const float* gp = &g_gaps[BATCH * C1N + b * C2N + g * 8];
        #pragma unroll
        for (int c = 0; c < 8; c++) a = fmaf(wc2[o * 8 + c] * INV2, gp[c], a);
        s_m2[t] = fmaxf(a, 0.f);
    }
    __syncthreads();
    if (t < 32) {
        int bb = t >> 3, gg = t & 7;
        int base = bb * 64 + gg * 8;
        float nr = 0.f;
        #pragma unroll
        for (int j = 0; j < 8; j++) { float m = s_m2[base + j]; nr += m * m; }
        float lg[8]; float mx = -1e30f;
        #pragma unroll
        for (int j = 0; j < 8; j++) { lg[j] = s_m1[base + j] * nr; mx = fmaxf(mx, lg[j]); }
        float Z = 0.f;
        #pragma unroll
        for (int j = 0; j < 8; j++) { lg[j] = expf(lg[j] - mx); Z += lg[j]; }
        float iz = 1.f / Z;
        #pragma unroll
        for (int j = 0; j < 8; j++) s_cw[base + j] = lg[j] * iz;
    }
    __syncthreads();
    const float A = rsqrtf(1.f + 1e-5f);
    #pragma unroll
    for (int k = 0; k < 4; k++) {            // this CTA's 1024-elem slice of [b][c][o]
        int i = blockIdx.x * 1024 + k * 256 + t;
        int bb = i >> 12, co = i & 4095, cc = co >> 6, oo = co & 63;
        g_w3t[i] = gamma[oo] * A * wf[oo * 64 + cc] * s_cw[bb * 64 + cc];
    }
    if (blockIdx.x == 0 && t < 64) {
        float ws = 0.f;
        for (int c = 0; c < 64; c++) ws += wf[t * 64 + c];
        float Ao = gamma[t] * A;
        g_s3[t] = Ao * ws;
        g_t3[t] = Ao * bf[t] + beta[t];
    }
}

// ---- kernel 3: per-block spatial attention (lean registers, high occupancy) ----
__global__ void __launch_bounds__(256) k_spa(const float* __restrict__ wlin,
                                             const float* __restrict__ blin) {
    __shared__ __align__(16) float s_p1[64];
    __shared__ float s_x1t[256], s_p2[256], s_red[18];
    __shared__ float s_acc[8 * 256];
    const float LOG2E = 1.4426950408889634f;
    int tid = threadIdx.x, wid = tid >> 5, lane = tid & 31;
    int blk = blockIdx.x;                 // = b*256 + n
    if (tid < 64) s_p1[tid] = g_pos1[blk * 64 + tid];
    s_p2[tid] = g_pos2[blk * 256 + tid];
    __syncthreads();
    float acc_t = blin[tid];
    const float4* wr = (const float4*)(wlin + tid * 64);
    #pragma unroll
    for (int c4 = 0; c4 < 16; c4++) {
        float4 w = wr[c4];
        acc_t += w.x * s_p1[c4 * 4 + 0] + w.y * s_p1[c4 * 4 + 1]
               + w.z * s_p1[c4 * 4 + 2] + w.w * s_p1[c4 * 4 + 3];
    }
    acc_t *= LOG2E;                       // exp(z) = exp2(z*log2e)
    s_x1t[tid] = acc_t;
    float vmax = acc_t, vmin = acc_t;
    #pragma unroll
    for (int o = 16; o; o >>= 1) {
        vmax = fmaxf(vmax, __shfl_xor_sync(0xffffffffu, vmax, o));
        vmin = fminf(vmin, __shfl_xor_sync(0xffffffffu, vmin, o));
    }
    if (lane == 0) { s_red[wid] = vmax; s_red[8 + wid] = vmin; }
    __syncthreads();
    if (tid == 0) {
        float mx = s_red[0], mn = s_red[8];
        #pragma unroll
        for (int w = 1; w < 8; w++) { mx = fmaxf(mx, s_red[w]); mn = fminf(mn, s_red[8 + w]); }
        s_red[16] = mx; s_red[17] = mn;
    }
    __syncthreads();
    float xmax = s_red[16], xmin = s_red[17];

    float x1r[8];
    #pragma unroll
    for (int j = 0; j < 8; j++) x1r[j] = s_x1t[lane + 32 * j];

    float accl[8];
    #pragma unroll
    for (int j = 0; j < 8; j++) accl[j] = 0.f;

    #pragma unroll 2
    for (int q = wid; q < 256; q += 8) {
        float p = s_p2[q];
        float rm = (p >= 0.f) ? p * xmax : p * xmin;   // exact row max (log2 domain)
        float e[8]; float sum = 0.f;
        #pragma unroll
        for (int j = 0; j < 8; j++) {
            float v = ex2f(fmaf(p, x1r[j], -rm));      // single MUFU.EX2
            e[j] = v; sum += v;
        }
        #pragma unroll
        for (int o = 16; o; o >>= 1) sum += __shfl_xor_sync(0xffffffffu, sum, o);
        float coef = __fdividef(p, sum);
        #pragma unroll
        for (int j = 0; j < 8; j++) accl[j] = fmaf(coef, e[j], accl[j]);
    }
    #pragma unroll
    for (int j = 0; j < 8; j++) s_acc[wid * 256 + lane + 32 * j] = accl[j];
    __syncthreads();
    float v = 0.f;
    #pragma unroll
    for (int w = 0; w < 8; w++) v += s_acc[w * 256 + tid];
    g_spa[blk * 256 + tid] = v;
}

// ---- kernel 4: fused conv; 8 outputs x 8 pixels / thread, deep-unrolled loads ----
// grid = b*256 + n (one full row per CTA). Pixel-pair packed FFMA2, dup weights.
__global__ void __launch_bounds__(256) k_fuse(const float* __restrict__ x2,
                                              float* __restrict__ out) {
    __shared__ __align__(16) float s_wd[C2N * 128];  // [c][2o] duplicated weights (32KB)
    __shared__ float s_s3[64], s_t3[64];
    int tid = threadIdx.x;
    int blk = blockIdx.x;
    int b = blk >> 8;
    int n = blk & 255;
    int opart = tid >> 5;                // warp-uniform: outputs [opart*8, +8)
    int pixg  = tid & 31;                // pixels pixg*8 .. +7 within row
    int p0 = n * 256 + pixg * 8;
    int obase = opart * 8;

    // re-zero the gap accumulators for the next graph replay
    if (blk < 3) {
        int i = blk * 256 + tid;
        if (i < BATCH * C1N + BATCH * C2N) g_gaps[i] = 0.f;
    }

    {   // build duplicated weight tile: each float4 of g_w3t -> two float4 of dups
        const float4* gw = (const float4*)&g_w3t[b * 4096];
        #pragma unroll
        for (int k = 0; k < 4; k++) {
            int g = k * 256 + tid;        // float4 index: c = g>>4, o4 = g&15
            float4 w = gw[g];
            float* dst = &s_wd[(g >> 4) * 128 + (g & 15) * 8];
            ((float4*)dst)[0] = make_float4(w.x, w.x, w.y, w.y);
            ((float4*)dst)[1] = make_float4(w.z, w.z, w.w, w.w);
        }
        if (tid < 64) { s_s3[tid] = g_s3[tid]; s_t3[tid] = g_t3[tid]; }
    }
    __syncthreads();

    unsigned long long acc[32];          // [o(0..7)][pixel-pair(0..3)]
    #pragma unroll
    for (int j = 0; j < 32; j++) acc[j] = 0ull;

    const double2* xb = (const double2*)(x2 + (size_t)b * C2N * NPIX2 + p0);
    #pragma unroll 4
    for (int c = 0; c < 64; c++) {
        // channel stride in double2 units = NPIX2/4 = 16384 = 1<<14
        double2 xv0 = xb[(size_t)c << 14];           // pixels 0..3 (2 packed pairs)
        double2 xv1 = xb[((size_t)c << 14) + 1];     // pixels 4..7
        unsigned long long xp[4] = {
            __double_as_longlong(xv0.x), __double_as_longlong(xv0.y),
            __double_as_longlong(xv1.x), __double_as_longlong(xv1.y)};
        const double2* wd = (const double2*)&s_wd[c * 128 + obase * 2];
        double2 wv0 = wd[0], wv1 = wd[1], wv2 = wd[2], wv3 = wd[3];
        unsigned long long w[8] = {
            __double_as_longlong(wv0.x), __double_as_longlong(wv0.y),
            __double_as_longlong(wv1.x), __double_as_longlong(wv1.y),
            __double_as_longlong(wv2.x), __double_as_longlong(wv2.y),
            __double_as_longlong(wv3.x), __double_as_longlong(wv3.y)};
        #pragma unroll
        for (int o = 0; o < 8; o++) {
            #pragma unroll
            for (int k = 0; k < 4; k++)
                asm("fma.rn.f32x2 %0, %1, %2, %0;" : "+l"(acc[4*o+k]) : "l"(w[o]), "l"(xp[k]));
        }
    }
    float4 sv0 = *(const float4*)&g_spa[(size_t)b * NPIX2 + p0];
    float4 sv1 = *(const float4*)&g_spa[(size_t)b * NPIX2 + p0 + 4];
    float svk[8] = {sv0.x, sv0.y, sv0.z, sv0.w, sv1.x, sv1.y, sv1.z, sv1.w};
    float* ob = out + (size_t)b * C2N * NPIX2 + p0;
    #pragma unroll
    for (int o = 0; o < 8; o++) {
        int oo = obase + o;
        float s3 = s_s3[oo], t3 = s_t3[oo];
        float v[8];
        #pragma unroll
        for (int k = 0; k < 4; k++)
            asm("mov.b64 {%0, %1}, %2;" : "=f"(v[2*k]), "=f"(v[2*k+1]) : "l"(acc[4*o+k]));
        float r[8];
        #pragma unroll
        for (int j = 0; j < 8; j++) r[j] = fmaxf(fmaf(s3, svk[j], v[j]) + t3, 0.f);
        ((float4*)(ob + ((size_t)oo << 16)))[0] = make_float4(r[0], r[1], r[2], r[3]);
        ((float4*)(ob + ((size_t)oo << 16)))[1] = make_float4(r[4], r[5], r[6], r[7]);
    }
}

extern "C" void kernel_launch(void* const* d_in, const int* in_sizes, int n_in,
                              void* d_out, int out_size) {
    const float* x1    = (const float*)d_in[0];
    const float* x2    = (const float*)d_in[1];
    const float* wc1   = (const float*)d_in[2];
    const float* bc1   = (const float*)d_in[3];
    const float* wc2   = (const float*)d_in[4];
    const float* bc2   = (const float*)d_in[5];
    const float* wp1   = (const float*)d_in[6];
    const float* bp1   = (const float*)d_in[7];
    const float* wp2   = (const float*)d_in[8];
    const float* bp2   = (const float*)d_in[9];
    const float* wlin  = (const float*)d_in[10];
    const float* blin  = (const float*)d_in[11];
    const float* wf    = (const float*)d_in[12];
    const float* bf    = (const float*)d_in[13];
    const float* gamma = (const float*)d_in[14];
    const float* beta  = (const float*)d_in[15];
    float* out = (float*)d_out;

    k_pos <<<256 + 1024, 256>>>(x1, wp1, bp1, x2, wp2, bp2);
    k_w3  <<<16, 256>>>(wc1, bc1, wc2, bc2, wf, bf, gamma, beta);
    k_spa <<<BATCH * NB, 256>>>(wlin, blin);
    k_fuse<<<BATCH * NB, 256>>>(x2, out);
}